// round 10
// baseline (speedup 1.0000x reference)
#include <cuda_runtime.h>
#include <cuda_bf16.h>
#include <cstdint>

#define N_NODES 6144
#define HEADS 4
#define FH 64
#define FIN 512
#define NCLS 40
#define MAX_DEG 128
#define NCAT 256            // HEADS*FH

#define GEMM_BLOCKS 96
#define CSR_BLOCKS 192

// ---------------- device scratch ----------------
__device__ int   g_col[N_NODES * MAX_DEG];
__device__ int   g_len[N_NODES];
__device__ float g_Wh[N_NODES * NCAT];      // [node][head*64+fh]
__device__ float g_f14[N_NODES * 4];        // [node][head]
__device__ float g_f24[N_NODES * 4];
__device__ float g_hcat[N_NODES * NCAT];
__device__ float g_Who[N_NODES * NCLS];
__device__ float g_f1o[N_NODES];
__device__ float g_f2o[N_NODES];
__device__ __nv_bfloat16 g_Whi[NCAT * FIN]; // [n=head*64+fh][k]
__device__ __nv_bfloat16 g_Wlo[NCAT * FIN];

// ---------------- helpers ----------------
__device__ __forceinline__ float warpMax(float v) {
#pragma unroll
    for (int o = 16; o; o >>= 1) v = fmaxf(v, __shfl_xor_sync(0xffffffffu, v, o));
    return v;
}
__device__ __forceinline__ float warpSum(float v) {
#pragma unroll
    for (int o = 16; o; o >>= 1) v += __shfl_xor_sync(0xffffffffu, v, o);
    return v;
}
__device__ __forceinline__ float lrelu(float x) { return x > 0.f ? x : 0.2f * x; }
__device__ __forceinline__ float elu(float x) { return x > 0.f ? x : (expf(x) - 1.f); }

__device__ __forceinline__ void ldsm_x4(uint32_t* r, uint32_t addr) {
    asm volatile("ldmatrix.sync.aligned.m8n8.x4.shared.b16 {%0,%1,%2,%3}, [%4];"
        : "=r"(r[0]), "=r"(r[1]), "=r"(r[2]), "=r"(r[3]) : "r"(addr));
}
__device__ __forceinline__ void mma16816(float* d, const uint32_t* a, const uint32_t* b) {
    asm volatile("mma.sync.aligned.m16n8k16.row.col.f32.bf16.bf16.f32 "
        "{%0,%1,%2,%3}, {%4,%5,%6,%7}, {%8,%9}, {%0,%1,%2,%3};"
        : "+f"(d[0]), "+f"(d[1]), "+f"(d[2]), "+f"(d[3])
        : "r"(a[0]), "r"(a[1]), "r"(a[2]), "r"(a[3]), "r"(b[0]), "r"(b[1]));
}
__device__ __forceinline__ uint32_t pack_bf16(float a, float b) {
    return ((uint32_t)__bfloat16_as_ushort(__float2bfloat16(b)) << 16) |
           (uint32_t)__bfloat16_as_ushort(__float2bfloat16(a));
}
__device__ __forceinline__ float bf_hi(float v) {
    return __bfloat162float(__float2bfloat16(v));
}

// ============ K0: W transpose + hi/lo split (tiny) ============
__global__ __launch_bounds__(256) void wconv_kernel(const float* __restrict__ W) {
    int i = blockIdx.x * 256 + threadIdx.x;           // over 131072 elements
    for (; i < NCAT * FIN; i += gridDim.x * 256) {
        int n = i >> 9;                // /FIN
        int k = i & (FIN - 1);
        int head = n >> 6, fh = n & 63;
        float v = W[((size_t)head * FIN + k) * FH + fh];
        float h = bf_hi(v);
        g_Whi[i] = __float2bfloat16(v);
        g_Wlo[i] = __float2bfloat16(v - h);
    }
}

// ============ K1: fused HMMA GEMM (on-the-fly x split) + adjacency compaction ============
#define SROW 80
#define NCHUNK 48   // 3 segments x 16 k-chunks of 32

__global__ __launch_bounds__(256) void fused_gemm_csr(
    const float* __restrict__ x, const float* __restrict__ adj) {
    __shared__ __align__(16) char sA[2][128 * SROW];
    __shared__ __align__(16) char sB[2][128 * SROW];
    int tid = threadIdx.x;
    int lane = tid & 31, wid = tid >> 5;

    if (blockIdx.x < GEMM_BLOCKS) {
        int wm = wid & 3, wn = wid >> 2;
        int m0 = (blockIdx.x >> 1) * 128;
        int nh = blockIdx.x & 1;
        const __nv_bfloat16* Blist[3] = {g_Whi, g_Whi, g_Wlo};

        int crow = tid >> 1;
        int khalf = tid & 1;            // 16-k half within chunk

        float acc[2][8][4];
#pragma unroll
        for (int i = 0; i < 2; i++)
#pragma unroll
            for (int j = 0; j < 8; j++)
#pragma unroll
                for (int q = 0; q < 4; q++) acc[i][j][q] = 0.f;

        int g = lane >> 3;
        int arow_lo = (lane & 7) + (g & 1) * 8;
        int ach_sel = g >> 1;
        int brow_add = (g >> 1) * 8;
        int bch_sel = g & 1;

        uint32_t sAb[2], sBb[2];
        sAb[0] = (uint32_t)__cvta_generic_to_shared(sA[0]);
        sAb[1] = (uint32_t)__cvta_generic_to_shared(sA[1]);
        sBb[0] = (uint32_t)__cvta_generic_to_shared(sB[0]);
        sBb[1] = (uint32_t)__cvta_generic_to_shared(sB[1]);

        const float4* xrow = reinterpret_cast<const float4*>(
            x + (size_t)(m0 + crow) * FIN) + khalf * 4;

        // prologue: chunk 0 (seg 0 = hi path)
        {
            float4 fa[4];
#pragma unroll
            for (int q = 0; q < 4; q++) fa[q] = xrow[q];
            uint4 pb0 = reinterpret_cast<const uint4*>(
                g_Whi + (size_t)(nh * 128 + crow) * FIN)[khalf * 2];
            uint4 pb1 = reinterpret_cast<const uint4*>(
                g_Whi + (size_t)(nh * 128 + crow) * FIN)[khalf * 2 + 1];
            uint32_t pk[8];
#pragma unroll
            for (int q = 0; q < 4; q++) {
                pk[q * 2]     = pack_bf16(fa[q].x, fa[q].y);
                pk[q * 2 + 1] = pack_bf16(fa[q].z, fa[q].w);
            }
            char* ab = sA[0] + crow * SROW + khalf * 32;
            *reinterpret_cast<uint4*>(ab)      = make_uint4(pk[0], pk[1], pk[2], pk[3]);
            *reinterpret_cast<uint4*>(ab + 16) = make_uint4(pk[4], pk[5], pk[6], pk[7]);
            char* bb = sB[0] + crow * SROW + khalf * 32;
            *reinterpret_cast<uint4*>(bb)      = pb0;
            *reinterpret_cast<uint4*>(bb + 16) = pb1;
        }
        __syncthreads();

        float4 prA[4];
        uint4 prB[2];
        for (int it = 0; it < NCHUNK; it++) {
            int buf = it & 1;
            bool more = (it + 1 < NCHUNK);
            int nseg = 0;
            if (more) {
                int nit = it + 1;
                nseg = nit >> 4;
                int k0 = (nit & 15) * 32;
#pragma unroll
                for (int q = 0; q < 4; q++) prA[q] = xrow[(k0 >> 2) + q];
                const uint4* bp = reinterpret_cast<const uint4*>(
                    Blist[nseg] + (size_t)(nh * 128 + crow) * FIN + k0) + khalf * 2;
                prB[0] = bp[0]; prB[1] = bp[1];
            }
#pragma unroll
            for (int kt = 0; kt < 2; kt++) {
                uint32_t afr[2][4];
#pragma unroll
                for (int mi = 0; mi < 2; mi++) {
                    int row = wm * 32 + mi * 16 + arow_lo;
                    int ch = kt * 2 + ach_sel;
                    ldsm_x4(afr[mi], sAb[buf] + row * SROW + ch * 16);
                }
                uint32_t bfr[4][4];
#pragma unroll
                for (int ni4 = 0; ni4 < 4; ni4++) {
                    int nrow = wn * 64 + ni4 * 16 + (lane & 7) + brow_add;
                    int ch = kt * 2 + bch_sel;
                    ldsm_x4(bfr[ni4], sBb[buf] + nrow * SROW + ch * 16);
                }
#pragma unroll
                for (int mi = 0; mi < 2; mi++)
#pragma unroll
                    for (int ni4 = 0; ni4 < 4; ni4++) {
                        mma16816(acc[mi][ni4 * 2], afr[mi], &bfr[ni4][0]);
                        mma16816(acc[mi][ni4 * 2 + 1], afr[mi], &bfr[ni4][2]);
                    }
            }
            if (more) {
                int nb = buf ^ 1;
                uint32_t pk[8];
                if (nseg == 1) {   // lo part of x
#pragma unroll
                    for (int q = 0; q < 4; q++) {
                        pk[q * 2]     = pack_bf16(prA[q].x - bf_hi(prA[q].x),
                                                  prA[q].y - bf_hi(prA[q].y));
                        pk[q * 2 + 1] = pack_bf16(prA[q].z - bf_hi(prA[q].z),
                                                  prA[q].w - bf_hi(prA[q].w));
                    }
                } else {           // hi part
#pragma unroll
                    for (int q = 0; q < 4; q++) {
                        pk[q * 2]     = pack_bf16(prA[q].x, prA[q].y);
                        pk[q * 2 + 1] = pack_bf16(prA[q].z, prA[q].w);
                    }
                }
                char* ab = sA[nb] + crow * SROW + khalf * 32;
                *reinterpret_cast<uint4*>(ab)      = make_uint4(pk[0], pk[1], pk[2], pk[3]);
                *reinterpret_cast<uint4*>(ab + 16) = make_uint4(pk[4], pk[5], pk[6], pk[7]);
                char* bb = sB[nb] + crow * SROW + khalf * 32;
                *reinterpret_cast<uint4*>(bb)      = prB[0];
                *reinterpret_cast<uint4*>(bb + 16) = prB[1];
            }
            __syncthreads();
        }

        // epilogue: Wh in [node][256] concat layout
#pragma unroll
        for (int mi = 0; mi < 2; mi++) {
#pragma unroll
            for (int ni = 0; ni < 8; ni++) {
                int row = m0 + wm * 32 + mi * 16 + (lane >> 2);
                int col = nh * 128 + wn * 64 + ni * 8 + (lane & 3) * 2;
                *reinterpret_cast<float2*>(g_Wh + (size_t)row * NCAT + col) =
                    make_float2(acc[mi][ni][0], acc[mi][ni][1]);
                *reinterpret_cast<float2*>(g_Wh + (size_t)(row + 8) * NCAT + col) =
                    make_float2(acc[mi][ni][2], acc[mi][ni][3]);
            }
        }
    } else {
        // ---- CSR path ----
        int wid2 = (blockIdx.x - GEMM_BLOCKS) * 8 + wid;
        unsigned lt = (1u << lane) - 1u;
        for (int rr = 0; rr < 4; rr++) {
            int row = wid2 * 4 + rr;
            const float4* rp = reinterpret_cast<const float4*>(adj + (size_t)row * N_NODES);
            int* outp = g_col + (size_t)row * MAX_DEG;
            int count = 0;
            for (int it = 0; it < N_NODES / 128; it += 4) {
                float4 v[4];
#pragma unroll
                for (int u = 0; u < 4; u++) v[u] = rp[(it + u) * 32 + lane];
#pragma unroll
                for (int u = 0; u < 4; u++) {
                    float4 vv = v[u];
                    int c0 = vv.x > 0.f, c1 = vv.y > 0.f, c2 = vv.z > 0.f, c3 = vv.w > 0.f;
                    unsigned m0b = __ballot_sync(0xffffffffu, c0);
                    unsigned m1b = __ballot_sync(0xffffffffu, c1);
                    unsigned m2b = __ballot_sync(0xffffffffu, c2);
                    unsigned m3b = __ballot_sync(0xffffffffu, c3);
                    int before = __popc(m0b & lt) + __popc(m1b & lt) + __popc(m2b & lt) + __popc(m3b & lt);
                    int pos = count + before;
                    int col0 = ((it + u) * 32 + lane) * 4;
                    if (c0) { if (pos < MAX_DEG) outp[pos] = col0;     pos++; }
                    if (c1) { if (pos < MAX_DEG) outp[pos] = col0 + 1; pos++; }
                    if (c2) { if (pos < MAX_DEG) outp[pos] = col0 + 2; pos++; }
                    if (c3) { if (pos < MAX_DEG) outp[pos] = col0 + 3; pos++; }
                    count += __popc(m0b) + __popc(m1b) + __popc(m2b) + __popc(m3b);
                }
            }
            if (lane == 0) g_len[row] = count < MAX_DEG ? count : MAX_DEG;
        }
    }
}

// ============ K2: f1/f2 (packed [node][head]) — warp per node ============
__global__ __launch_bounds__(256) void compute_f_kernel(
    const float* __restrict__ a1, const float* __restrict__ a2) {
    int warp = threadIdx.x >> 5, lane = threadIdx.x & 31;
    int i = blockIdx.x * 8 + warp;
    const float4* wr = reinterpret_cast<const float4*>(g_Wh + (size_t)i * NCAT + lane * 8);
    float4 v0 = wr[0], v1 = wr[1];
    const float4* a1p = reinterpret_cast<const float4*>(a1 + lane * 8);
    const float4* a2p = reinterpret_cast<const float4*>(a2 + lane * 8);
    float4 a10 = a1p[0], a11 = a1p[1], a20 = a2p[0], a21 = a2p[1];
    float s1 = v0.x * a10.x + v0.y * a10.y + v0.z * a10.z + v0.w * a10.w
             + v1.x * a11.x + v1.y * a11.y + v1.z * a11.z + v1.w * a11.w;
    float s2 = v0.x * a20.x + v0.y * a20.y + v0.z * a20.z + v0.w * a20.w
             + v1.x * a21.x + v1.y * a21.y + v1.z * a21.z + v1.w * a21.w;
#pragma unroll
    for (int o = 4; o; o >>= 1) {
        s1 += __shfl_down_sync(0xffffffffu, s1, o, 8);
        s2 += __shfl_down_sync(0xffffffffu, s2, o, 8);
    }
    if ((lane & 7) == 0) {
        g_f14[i * 4 + (lane >> 3)] = s1;
        g_f24[i * 4 + (lane >> 3)] = s2;
    }
}

// ============ K3: all-head sparse attention + ELU -> hcat ============
__global__ __launch_bounds__(256) void attn_heads_kernel() {
    __shared__ float sw[8][4][MAX_DEG];   // 16 KB
    __shared__ int   scol[8][MAX_DEG];    // 4 KB
    int warp = threadIdx.x >> 5, lane = threadIdx.x & 31;
    int i = blockIdx.x * 8 + warp;
    int len = g_len[i];
    const int* cols = g_col + (size_t)i * MAX_DEG;
    float4 f1v = *reinterpret_cast<const float4*>(g_f14 + i * 4);

    float m0 = -1e30f, m1 = -1e30f, m2 = -1e30f, m3 = -1e30f;
    for (int t = lane; t < len; t += 32) {
        int j = __ldg(cols + t);
        scol[warp][t] = j;
        float4 f2v = *reinterpret_cast<const float4*>(g_f24 + j * 4);
        float e0 = lrelu(f1v.x + f2v.x);
        float e1 = lrelu(f1v.y + f2v.y);
        float e2 = lrelu(f1v.z + f2v.z);
        float e3 = lrelu(f1v.w + f2v.w);
        sw[warp][0][t] = e0; sw[warp][1][t] = e1;
        sw[warp][2][t] = e2; sw[warp][3][t] = e3;
        m0 = fmaxf(m0, e0); m1 = fmaxf(m1, e1);
        m2 = fmaxf(m2, e2); m3 = fmaxf(m3, e3);
    }
    m0 = warpMax(m0); m1 = warpMax(m1); m2 = warpMax(m2); m3 = warpMax(m3);
    float s0 = 0.f, s1 = 0.f, s2 = 0.f, s3 = 0.f;
    for (int t = lane; t < len; t += 32) {
        float w0 = expf(sw[warp][0][t] - m0);
        float w1 = expf(sw[warp][1][t] - m1);
        float w2 = expf(sw[warp][2][t] - m2);
        float w3 = expf(sw[warp][3][t] - m3);
        sw[warp][0][t] = w0; sw[warp][1][t] = w1;
        sw[warp][2][t] = w2; sw[warp][3][t] = w3;
        s0 += w0; s1 += w1; s2 += w2; s3 += w3;
    }
    s0 = warpSum(s0); s1 = warpSum(s1); s2 = warpSum(s2); s3 = warpSum(s3);
    __syncwarp();

    int h = lane >> 3;
    float inv = 1.f / (h == 0 ? s0 : h == 1 ? s1 : h == 2 ? s2 : s3);
    float acc[8] = {0.f, 0.f, 0.f, 0.f, 0.f, 0.f, 0.f, 0.f};
    const float* whb = g_Wh;
    int t = 0;
    for (; t + 2 <= len; t += 2) {
        int j0 = scol[warp][t], j1 = scol[warp][t + 1];
        float w0 = sw[warp][h][t], w1 = sw[warp][h][t + 1];
        const float4* p0 = reinterpret_cast<const float4*>(whb + (size_t)j0 * NCAT + lane * 8);
        const float4* p1 = reinterpret_cast<const float4*>(whb + (size_t)j1 * NCAT + lane * 8);
        float4 x0 = p0[0], x1 = p0[1], y0 = p1[0], y1 = p1[1];
        acc[0] += w0 * x0.x + w1 * y0.x;
        acc[1] += w0 * x0.y + w1 * y0.y;
        acc[2] += w0 * x0.z + w1 * y0.z;
        acc[3] += w0 * x0.w + w1 * y0.w;
        acc[4] += w0 * x1.x + w1 * y1.x;
        acc[5] += w0 * x1.y + w1 * y1.y;
        acc[6] += w0 * x1.z + w1 * y1.z;
        acc[7] += w0 * x1.w + w1 * y1.w;
    }
    if (t < len) {
        int j0 = scol[warp][t];
        float w0 = sw[warp][h][t];
        const float4* p0 = reinterpret_cast<const float4*>(whb + (size_t)j0 * NCAT + lane * 8);
        float4 x0 = p0[0], x1 = p0[1];
        acc[0] += w0 * x0.x; acc[1] += w0 * x0.y;
        acc[2] += w0 * x0.z; acc[3] += w0 * x0.w;
        acc[4] += w0 * x1.x; acc[5] += w0 * x1.y;
        acc[6] += w0 * x1.z; acc[7] += w0 * x1.w;
    }
    float4 o0 = make_float4(elu(acc[0] * inv), elu(acc[1] * inv),
                            elu(acc[2] * inv), elu(acc[3] * inv));
    float4 o1 = make_float4(elu(acc[4] * inv), elu(acc[5] * inv),
                            elu(acc[6] * inv), elu(acc[7] * inv));
    float4* dst = reinterpret_cast<float4*>(g_hcat + (size_t)i * NCAT + lane * 8);
    dst[0] = o0; dst[1] = o1;
}

// ============ K4: Who = hcat @ Wo, fused f1o/f2o ============
__global__ __launch_bounds__(256) void out_proj_kernel(
    const float* __restrict__ Wo, const float* __restrict__ ao1,
    const float* __restrict__ ao2) {
    __shared__ float sWo[NCAT * NCLS];
    for (int t = threadIdx.x; t < NCAT * NCLS; t += blockDim.x) sWo[t] = Wo[t];
    __syncthreads();
    int warp = threadIdx.x >> 5, lane = threadIdx.x & 31;
    int i = blockIdx.x * 8 + warp;
    const float* hr = g_hcat + (size_t)i * NCAT;
    bool hi = lane < (NCLS - 32);
    float acc0 = 0.f, acc1 = 0.f;
    for (int k0 = 0; k0 < NCAT; k0 += 32) {
        float hv = hr[k0 + lane];
#pragma unroll
        for (int kk = 0; kk < 32; kk++) {
            float hb = __shfl_sync(0xffffffffu, hv, kk);
            const float* wrow = sWo + (k0 + kk) * NCLS;
            acc0 += hb * wrow[lane];
            if (hi) acc1 += hb * wrow[32 + lane];
        }
    }
    g_Who[(size_t)i * NCLS + lane] = acc0;
    if (hi) g_Who[(size_t)i * NCLS + 32 + lane] = acc1;
    float v1 = acc0 * ao1[lane] + (hi ? acc1 * ao1[32 + lane] : 0.f);
    float v2 = acc0 * ao2[lane] + (hi ? acc1 * ao2[32 + lane] : 0.f);
    v1 = warpSum(v1);
    v2 = warpSum(v2);
    if (lane == 0) { g_f1o[i] = v1; g_f2o[i] = v2; }
}

// ============ K5: output sparse attention + ELU + log_softmax ============
__global__ __launch_bounds__(256) void attn_out_kernel(float* __restrict__ out) {
    __shared__ float sw[8][MAX_DEG];
    __shared__ int   sc[8][MAX_DEG];
    int warp = threadIdx.x >> 5, lane = threadIdx.x & 31;
    int i = blockIdx.x * 8 + warp;
    int len = g_len[i];
    const int* cols = g_col + (size_t)i * MAX_DEG;
    float f1i = g_f1o[i];

    float m = -1e30f;
    for (int t = lane; t < len; t += 32) {
        int j = __ldg(cols + t);
        sc[warp][t] = j;
        float e = lrelu(f1i + g_f2o[j]);
        sw[warp][t] = e;
        m = fmaxf(m, e);
    }
    m = warpMax(m);
    float s = 0.f;
    for (int t = lane; t < len; t += 32) {
        float we = expf(sw[warp][t] - m);
        sw[warp][t] = we;
        s += we;
    }
    s = warpSum(s);
    float inv = 1.f / s;
    __syncwarp();

    bool hi = lane < (NCLS - 32);
    float accA[4] = {0.f, 0.f, 0.f, 0.f};
    float accB[2] = {0.f, 0.f};
    int t = 0;
    for (; t + 4 <= len; t += 4) {
#pragma unroll
        for (int u = 0; u < 4; u++) {
            int j = sc[warp][t + u];
            float wgt = sw[warp][t + u];
            const float* wr = g_Who + (size_t)j * NCLS;
            accA[u] += wgt * wr[lane];
            if (hi) accB[u & 1] += wgt * wr[32 + lane];
        }
    }
    for (; t < len; t++) {
        int j = sc[warp][t];
        float wgt = sw[warp][t];
        const float* wr = g_Who + (size_t)j * NCLS;
        accA[0] += wgt * wr[lane];
        if (hi) accB[0] += wgt * wr[32 + lane];
    }
    float v0 = elu((accA[0] + accA[1] + accA[2] + accA[3]) * inv);
    float v1 = hi ? elu((accB[0] + accB[1]) * inv) : -1e30f;
    float mm = warpMax(fmaxf(v0, v1));
    float se = expf(v0 - mm) + (hi ? expf(v1 - mm) : 0.f);
    se = warpSum(se);
    float lse = logf(se);
    out[(size_t)i * NCLS + lane] = v0 - mm - lse;
    if (hi) out[(size_t)i * NCLS + 32 + lane] = v1 - mm - lse;
}

// ---------------- launch ----------------
extern "C" void kernel_launch(void* const* d_in, const int* in_sizes, int n_in,
                              void* d_out, int out_size) {
    const float* x   = (const float*)d_in[0];
    const float* adj = (const float*)d_in[1];
    const float* W   = (const float*)d_in[2];
    const float* a1  = (const float*)d_in[3];
    const float* a2  = (const float*)d_in[4];
    const float* Wo  = (const float*)d_in[5];
    const float* ao1 = (const float*)d_in[6];
    const float* ao2 = (const float*)d_in[7];
    float* out = (float*)d_out;
    (void)in_sizes; (void)n_in; (void)out_size;

    wconv_kernel<<<128, 256>>>(W);
    fused_gemm_csr<<<GEMM_BLOCKS + CSR_BLOCKS, 256>>>(x, adj);
    compute_f_kernel<<<N_NODES / 8, 256>>>(a1, a2);
    attn_heads_kernel<<<N_NODES / 8, 256>>>();
    out_proj_kernel<<<N_NODES / 8, 256>>>(Wo, ao1, ao2);
    attn_out_kernel<<<N_NODES / 8, 256>>>(out);
}

// round 11
// speedup vs baseline: 1.5448x; 1.5448x over previous
#include <cuda_runtime.h>
#include <cuda_bf16.h>
#include <cstdint>

#define N_NODES 6144
#define HEADS 4
#define FH 64
#define FIN 512
#define NCLS 40
#define MAX_DEG 128
#define NCAT 256

#define GEMM_BLOCKS 96
#define CSR_BLOCKS 1536          // 4 rows per block
#define FUSED_SMEM 49216         // 2x24576 row bufs + scan scratch (GEMM uses 43008)

// ---------------- device scratch ----------------
__device__ int   g_col[N_NODES * MAX_DEG];
__device__ int   g_len[N_NODES];
__device__ float g_Wh[HEADS * N_NODES * FH];   // [head][node][fh]
__device__ float g_f1[HEADS * N_NODES];
__device__ float g_f2[HEADS * N_NODES];
__device__ float g_hcat[N_NODES * NCAT];       // [node][head*64+fh]
__device__ float g_Who[N_NODES * NCLS];
__device__ float g_f1o[N_NODES];
__device__ float g_f2o[N_NODES];
__device__ __nv_bfloat16 g_xhi[N_NODES * FIN];
__device__ __nv_bfloat16 g_xlo[N_NODES * FIN];
__device__ __nv_bfloat16 g_Whi[NCAT * FIN];    // [n=head*64+fh][k]
__device__ __nv_bfloat16 g_Wlo[NCAT * FIN];

// ---------------- helpers ----------------
__device__ __forceinline__ float warpMax(float v) {
#pragma unroll
    for (int o = 16; o; o >>= 1) v = fmaxf(v, __shfl_xor_sync(0xffffffffu, v, o));
    return v;
}
__device__ __forceinline__ float warpSum(float v) {
#pragma unroll
    for (int o = 16; o; o >>= 1) v += __shfl_xor_sync(0xffffffffu, v, o);
    return v;
}
__device__ __forceinline__ float lrelu(float x) { return x > 0.f ? x : 0.2f * x; }
__device__ __forceinline__ float elu(float x) { return x > 0.f ? x : (expf(x) - 1.f); }

__device__ __forceinline__ void ldsm_x4(uint32_t* r, uint32_t addr) {
    asm volatile("ldmatrix.sync.aligned.m8n8.x4.shared.b16 {%0,%1,%2,%3}, [%4];"
        : "=r"(r[0]), "=r"(r[1]), "=r"(r[2]), "=r"(r[3]) : "r"(addr));
}
__device__ __forceinline__ void mma16816(float* d, const uint32_t* a, const uint32_t* b) {
    asm volatile("mma.sync.aligned.m16n8k16.row.col.f32.bf16.bf16.f32 "
        "{%0,%1,%2,%3}, {%4,%5,%6,%7}, {%8,%9}, {%0,%1,%2,%3};"
        : "+f"(d[0]), "+f"(d[1]), "+f"(d[2]), "+f"(d[3])
        : "r"(a[0]), "r"(a[1]), "r"(a[2]), "r"(a[3]), "r"(b[0]), "r"(b[1]));
}
__device__ __forceinline__ float bf_hi(float v) {
    return __bfloat162float(__float2bfloat16(v));
}
#define CP_ASYNC16(dst, src) \
    asm volatile("cp.async.cg.shared.global [%0], [%1], 16;" :: "r"(dst), "l"(src) : "memory")
#define CP_COMMIT() asm volatile("cp.async.commit_group;" ::: "memory")
#define CP_WAIT1()  asm volatile("cp.async.wait_group 1;" ::: "memory")
#define CP_WAIT0()  asm volatile("cp.async.wait_group 0;" ::: "memory")

// ============ K0: x hi/lo split + W transpose/split ============
__global__ __launch_bounds__(256) void conv_kernel(
    const float* __restrict__ x, const float* __restrict__ W) {
    int tid = blockIdx.x * 256 + threadIdx.x;
    int stride = gridDim.x * 256;
    const float4* x4 = reinterpret_cast<const float4*>(x);
    for (int i = tid; i < N_NODES * FIN / 4; i += stride) {
        float4 v = x4[i];
        float vv[4] = {v.x, v.y, v.z, v.w};
#pragma unroll
        for (int u = 0; u < 4; u++) {
            __nv_bfloat16 h = __float2bfloat16(vv[u]);
            g_xhi[i * 4 + u] = h;
            g_xlo[i * 4 + u] = __float2bfloat16(vv[u] - __bfloat162float(h));
        }
    }
    for (int i = tid; i < NCAT * FIN; i += stride) {
        int n = i >> 9;
        int k = i & (FIN - 1);
        int head = n >> 6, fh = n & 63;
        float v = W[((size_t)head * FIN + k) * FH + fh];
        g_Whi[i] = __float2bfloat16(v);
        g_Wlo[i] = __float2bfloat16(v - bf_hi(v));
    }
}

// ============ K1: fused HMMA GEMM (+f1/f2 epilogue) + cp.async CSR scan ============
#define SROW 80
#define NCHUNK 48   // 3 segments x 16 k-chunks of 32

__global__ __launch_bounds__(256) void fused_gemm_csr(
    const float* __restrict__ adj,
    const float* __restrict__ a1, const float* __restrict__ a2) {
    extern __shared__ __align__(16) char smem_u[];
    int tid = threadIdx.x;
    int lane = tid & 31, wid = tid >> 5;

    if (blockIdx.x < GEMM_BLOCKS) {
        // ---------------- GEMM path (R5-proven) ----------------
        char* sAp[2] = {smem_u, smem_u + 10240};
        char* sBp[2] = {smem_u + 20480, smem_u + 30720};
        float* sa1f = reinterpret_cast<float*>(smem_u + 40960);
        float* sa2f = reinterpret_cast<float*>(smem_u + 41984);
        sa1f[tid] = a1[tid];
        sa2f[tid] = a2[tid];

        int wm = wid & 3, wn = wid >> 2;
        int m0 = (blockIdx.x >> 1) * 128;
        int nh = blockIdx.x & 1;
        const __nv_bfloat16* Alist[3] = {g_xhi, g_xlo, g_xhi};
        const __nv_bfloat16* Blist[3] = {g_Whi, g_Whi, g_Wlo};

        int crow = tid >> 1;
        int khalf = tid & 1;

        float acc[2][8][4];
#pragma unroll
        for (int i = 0; i < 2; i++)
#pragma unroll
            for (int j = 0; j < 8; j++)
#pragma unroll
                for (int q = 0; q < 4; q++) acc[i][j][q] = 0.f;

        int g = lane >> 3;
        int arow_lo = (lane & 7) + (g & 1) * 8;
        int ach_sel = g >> 1;
        int brow_add = (g >> 1) * 8;
        int bch_sel = g & 1;

        uint32_t sAb[2], sBb[2];
        sAb[0] = (uint32_t)__cvta_generic_to_shared(sAp[0]);
        sAb[1] = (uint32_t)__cvta_generic_to_shared(sAp[1]);
        sBb[0] = (uint32_t)__cvta_generic_to_shared(sBp[0]);
        sBb[1] = (uint32_t)__cvta_generic_to_shared(sBp[1]);

        // prologue: chunk 0
        {
            const uint4* ap = reinterpret_cast<const uint4*>(
                Alist[0] + (size_t)(m0 + crow) * FIN) + khalf * 2;
            const uint4* bp = reinterpret_cast<const uint4*>(
                Blist[0] + (size_t)(nh * 128 + crow) * FIN) + khalf * 2;
            uint4 a0 = ap[0], a1v = ap[1], b0 = bp[0], b1 = bp[1];
            char* ab = sAp[0] + crow * SROW + khalf * 32;
            char* bb = sBp[0] + crow * SROW + khalf * 32;
            *reinterpret_cast<uint4*>(ab) = a0;
            *reinterpret_cast<uint4*>(ab + 16) = a1v;
            *reinterpret_cast<uint4*>(bb) = b0;
            *reinterpret_cast<uint4*>(bb + 16) = b1;
        }
        __syncthreads();

        uint4 prA[2], prB[2];
        for (int it = 0; it < NCHUNK; it++) {
            int buf = it & 1;
            bool more = (it + 1 < NCHUNK);
            if (more) {
                int nit = it + 1;
                int seg = nit >> 4;
                int k0 = (nit & 15) * 32;
                const uint4* ap = reinterpret_cast<const uint4*>(
                    Alist[seg] + (size_t)(m0 + crow) * FIN + k0) + khalf * 2;
                const uint4* bp = reinterpret_cast<const uint4*>(
                    Blist[seg] + (size_t)(nh * 128 + crow) * FIN + k0) + khalf * 2;
                prA[0] = ap[0]; prA[1] = ap[1];
                prB[0] = bp[0]; prB[1] = bp[1];
            }
#pragma unroll
            for (int kt = 0; kt < 2; kt++) {
                uint32_t afr[2][4];
#pragma unroll
                for (int mi = 0; mi < 2; mi++) {
                    int row = wm * 32 + mi * 16 + arow_lo;
                    int ch = kt * 2 + ach_sel;
                    ldsm_x4(afr[mi], sAb[buf] + row * SROW + ch * 16);
                }
                uint32_t bfr[4][4];
#pragma unroll
                for (int ni4 = 0; ni4 < 4; ni4++) {
                    int nrow = wn * 64 + ni4 * 16 + (lane & 7) + brow_add;
                    int ch = kt * 2 + bch_sel;
                    ldsm_x4(bfr[ni4], sBb[buf] + nrow * SROW + ch * 16);
                }
#pragma unroll
                for (int mi = 0; mi < 2; mi++)
#pragma unroll
                    for (int ni4 = 0; ni4 < 4; ni4++) {
                        mma16816(acc[mi][ni4 * 2], afr[mi], &bfr[ni4][0]);
                        mma16816(acc[mi][ni4 * 2 + 1], afr[mi], &bfr[ni4][2]);
                    }
            }
            if (more) {
                int nb = buf ^ 1;
                char* ab = sAp[nb] + crow * SROW + khalf * 32;
                char* bb = sBp[nb] + crow * SROW + khalf * 32;
                *reinterpret_cast<uint4*>(ab) = prA[0];
                *reinterpret_cast<uint4*>(ab + 16) = prA[1];
                *reinterpret_cast<uint4*>(bb) = prB[0];
                *reinterpret_cast<uint4*>(bb + 16) = prB[1];
            }
            __syncthreads();
        }

        // epilogue: Wh store [head][node][fh] + fused f1/f2 (warp owns full head slice)
        int h = nh * 2 + wn;
#pragma unroll
        for (int mi = 0; mi < 2; mi++) {
#pragma unroll
            for (int ni = 0; ni < 8; ni++) {
                int row = m0 + wm * 32 + mi * 16 + (lane >> 2);
                int col = nh * 128 + wn * 64 + ni * 8 + (lane & 3) * 2;
                int head = col >> 6, fh = col & 63;
                float* base = g_Wh + (size_t)head * N_NODES * FH + fh;
                *reinterpret_cast<float2*>(base + (size_t)row * FH) =
                    make_float2(acc[mi][ni][0], acc[mi][ni][1]);
                *reinterpret_cast<float2*>(base + (size_t)(row + 8) * FH) =
                    make_float2(acc[mi][ni][2], acc[mi][ni][3]);
            }
            float p1a = 0.f, p2a = 0.f, p1b = 0.f, p2b = 0.f;
#pragma unroll
            for (int ni = 0; ni < 8; ni++) {
                int c0 = ni * 8 + (lane & 3) * 2;
                float A0 = sa1f[h * 64 + c0], A1 = sa1f[h * 64 + c0 + 1];
                float B0 = sa2f[h * 64 + c0], B1 = sa2f[h * 64 + c0 + 1];
                p1a += acc[mi][ni][0] * A0 + acc[mi][ni][1] * A1;
                p2a += acc[mi][ni][0] * B0 + acc[mi][ni][1] * B1;
                p1b += acc[mi][ni][2] * A0 + acc[mi][ni][3] * A1;
                p2b += acc[mi][ni][2] * B0 + acc[mi][ni][3] * B1;
            }
            p1a += __shfl_down_sync(0xffffffffu, p1a, 2, 4);
            p1a += __shfl_down_sync(0xffffffffu, p1a, 1, 4);
            p2a += __shfl_down_sync(0xffffffffu, p2a, 2, 4);
            p2a += __shfl_down_sync(0xffffffffu, p2a, 1, 4);
            p1b += __shfl_down_sync(0xffffffffu, p1b, 2, 4);
            p1b += __shfl_down_sync(0xffffffffu, p1b, 1, 4);
            p2b += __shfl_down_sync(0xffffffffu, p2b, 2, 4);
            p2b += __shfl_down_sync(0xffffffffu, p2b, 1, 4);
            if ((lane & 3) == 0) {
                int row = m0 + wm * 32 + mi * 16 + (lane >> 2);
                g_f1[h * N_NODES + row] = p1a;
                g_f2[h * N_NODES + row] = p2a;
                g_f1[h * N_NODES + row + 8] = p1b;
                g_f2[h * N_NODES + row + 8] = p2b;
            }
        }
    } else {
        // ---------------- CSR path: cp.async double-buffered row scan ----------------
        char* bufs[2] = {smem_u, smem_u + 24576};
        int* warr = reinterpret_cast<int*>(smem_u + 49152);
        int brow = (blockIdx.x - GEMM_BLOCKS) * 4;

        {   // prefetch row 0
            const char* src = reinterpret_cast<const char*>(adj + (size_t)brow * N_NODES);
            uint32_t d = (uint32_t)__cvta_generic_to_shared(bufs[0]);
#pragma unroll
            for (int u = 0; u < 6; u++)
                CP_ASYNC16(d + (tid + u * 256) * 16, src + (size_t)(tid + u * 256) * 16);
            CP_COMMIT();
        }
        for (int r = 0; r < 4; r++) {
            int buf = r & 1;
            if (r < 3) {
                const char* src = reinterpret_cast<const char*>(
                    adj + (size_t)(brow + r + 1) * N_NODES);
                uint32_t d = (uint32_t)__cvta_generic_to_shared(bufs[buf ^ 1]);
#pragma unroll
                for (int u = 0; u < 6; u++)
                    CP_ASYNC16(d + (tid + u * 256) * 16, src + (size_t)(tid + u * 256) * 16);
                CP_COMMIT();
                CP_WAIT1();
            } else {
                CP_WAIT0();
            }
            __syncthreads();

            const float4* bp = reinterpret_cast<const float4*>(bufs[buf]);
            float4 v[6];
#pragma unroll
            for (int u = 0; u < 6; u++) v[u] = bp[wid * 192 + u * 32 + lane];
            int msk[6];
            int cnt = 0;
#pragma unroll
            for (int u = 0; u < 6; u++) {
                int m = (v[u].x > 0.f) | ((v[u].y > 0.f) << 1) |
                        ((v[u].z > 0.f) << 2) | ((v[u].w > 0.f) << 3);
                msk[u] = m;
                cnt += __popc(m);
            }
            int incl = cnt;
#pragma unroll
            for (int o = 1; o < 32; o <<= 1) {
                int n = __shfl_up_sync(0xffffffffu, incl, o);
                if (lane >= o) incl += n;
            }
            if (lane == 31) warr[wid] = incl;
            __syncthreads();
            int bpre = 0;
#pragma unroll
            for (int w2 = 0; w2 < 8; w2++) bpre += (w2 < wid) ? warr[w2] : 0;
            int total8 = warr[0] + warr[1] + warr[2] + warr[3] +
                         warr[4] + warr[5] + warr[6] + warr[7];
            int row = brow + r;
            int* outp = g_col + (size_t)row * MAX_DEG;
            int pos = bpre + incl - cnt;
#pragma unroll
            for (int u = 0; u < 6; u++) {
                int m = msk[u];
                int col0 = (wid * 192 + u * 32 + lane) * 4;
                if (m & 1) { if (pos < MAX_DEG) outp[pos] = col0;     pos++; }
                if (m & 2) { if (pos < MAX_DEG) outp[pos] = col0 + 1; pos++; }
                if (m & 4) { if (pos < MAX_DEG) outp[pos] = col0 + 2; pos++; }
                if (m & 8) { if (pos < MAX_DEG) outp[pos] = col0 + 3; pos++; }
            }
            if (tid == 0) g_len[row] = total8 < MAX_DEG ? total8 : MAX_DEG;
            __syncthreads();
        }
    }
}

// ============ K2: per-head sparse attention + ELU -> hcat (R5 + float2 gathers) ============
__global__ __launch_bounds__(256) void attn_heads_kernel() {
    __shared__ float sw[8][MAX_DEG];
    __shared__ int   sc[8][MAX_DEG];
    int warp = threadIdx.x >> 5, lane = threadIdx.x & 31;
    int h = blockIdx.y;
    int i = blockIdx.x * 8 + warp;
    int len = g_len[i];
    const int* cols = g_col + (size_t)i * MAX_DEG;
    float f1i = g_f1[h * N_NODES + i];
    const float* f2h = g_f2 + (size_t)h * N_NODES;

    float m = -1e30f;
    for (int t = lane; t < len; t += 32) {
        int j = __ldg(cols + t);
        sc[warp][t] = j;
        float e = lrelu(f1i + f2h[j]);
        sw[warp][t] = e;
        m = fmaxf(m, e);
    }
    m = warpMax(m);
    float s = 0.f;
    for (int t = lane; t < len; t += 32) {
        float we = expf(sw[warp][t] - m);
        sw[warp][t] = we;
        s += we;
    }
    s = warpSum(s);
    float inv = 1.f / s;
    __syncwarp();

    const float* WhH = g_Wh + (size_t)h * N_NODES * FH;
    float2 a0 = {0.f, 0.f}, a1v = {0.f, 0.f}, a2v = {0.f, 0.f}, a3 = {0.f, 0.f};
    int t = 0;
    for (; t + 4 <= len; t += 4) {
        int j0 = sc[warp][t], j1 = sc[warp][t + 1];
        int j2 = sc[warp][t + 2], j3 = sc[warp][t + 3];
        float w0 = sw[warp][t], w1 = sw[warp][t + 1];
        float w2 = sw[warp][t + 2], w3 = sw[warp][t + 3];
        float2 v0 = *(reinterpret_cast<const float2*>(WhH + (size_t)j0 * FH) + lane);
        float2 v1 = *(reinterpret_cast<const float2*>(WhH + (size_t)j1 * FH) + lane);
        float2 v2 = *(reinterpret_cast<const float2*>(WhH + (size_t)j2 * FH) + lane);
        float2 v3 = *(reinterpret_cast<const float2*>(WhH + (size_t)j3 * FH) + lane);
        a0.x += w0 * v0.x; a0.y += w0 * v0.y;
        a1v.x += w1 * v1.x; a1v.y += w1 * v1.y;
        a2v.x += w2 * v2.x; a2v.y += w2 * v2.y;
        a3.x += w3 * v3.x; a3.y += w3 * v3.y;
    }
    for (; t < len; t++) {
        int j0 = sc[warp][t];
        float w0 = sw[warp][t];
        float2 v0 = *(reinterpret_cast<const float2*>(WhH + (size_t)j0 * FH) + lane);
        a0.x += w0 * v0.x; a0.y += w0 * v0.y;
    }
    float rx = a0.x + a1v.x + a2v.x + a3.x;
    float ry = a0.y + a1v.y + a2v.y + a3.y;
    float2 o = make_float2(elu(rx * inv), elu(ry * inv));
    *(reinterpret_cast<float2*>(g_hcat + (size_t)i * NCAT + h * FH) + lane) = o;
}

// ============ K3: Who = hcat @ Wo, fused f1o/f2o (R2-proven) ============
__global__ __launch_bounds__(256) void out_proj_kernel(
    const float* __restrict__ Wo, const float* __restrict__ ao1,
    const float* __restrict__ ao2) {
    __shared__ float sWo[NCAT * NCLS];
    for (int t = threadIdx.x; t < NCAT * NCLS; t += blockDim.x) sWo[t] = Wo[t];
    __syncthreads();
    int warp = threadIdx.x >> 5, lane = threadIdx.x & 31;
    int i = blockIdx.x * 8 + warp;
    const float* hr = g_hcat + (size_t)i * NCAT;
    bool hi = lane < (NCLS - 32);
    float acc0 = 0.f, acc1 = 0.f;
    for (int k0 = 0; k0 < NCAT; k0 += 32) {
        float hv = hr[k0 + lane];
#pragma unroll
        for (int kk = 0; kk < 32; kk++) {
            float hb = __shfl_sync(0xffffffffu, hv, kk);
            const float* wrow = sWo + (k0 + kk) * NCLS;
            acc0 += hb * wrow[lane];
            if (hi) acc1 += hb * wrow[32 + lane];
        }
    }
    g_Who[(size_t)i * NCLS + lane] = acc0;
    if (hi) g_Who[(size_t)i * NCLS + 32 + lane] = acc1;
    float v1 = acc0 * ao1[lane] + (hi ? acc1 * ao1[32 + lane] : 0.f);
    float v2 = acc0 * ao2[lane] + (hi ? acc1 * ao2[32 + lane] : 0.f);
    v1 = warpSum(v1);
    v2 = warpSum(v2);
    if (lane == 0) { g_f1o[i] = v1; g_f2o[i] = v2; }
}

// ============ K4: output sparse attention + ELU + log_softmax (R2-proven) ============
__global__ __launch_bounds__(256) void attn_out_kernel(float* __restrict__ out) {
    __shared__ float sw[8][MAX_DEG];
    __shared__ int   sc[8][MAX_DEG];
    int warp = threadIdx.x >> 5, lane = threadIdx.x & 31;
    int i = blockIdx.x * 8 + warp;
    int len = g_len[i];
    const int* cols = g_col + (size_t)i * MAX_DEG;
    float f1i = g_f1o[i];

    float m = -1e30f;
    for (int t = lane; t < len; t += 32) {
        int j = __ldg(cols + t);
        sc[warp][t] = j;
        float e = lrelu(f1i + g_f2o[j]);
        sw[warp][t] = e;
        m = fmaxf(m, e);
    }
    m = warpMax(m);
    float s = 0.f;
    for (int t = lane; t < len; t += 32) {
        float we = expf(sw[warp][t] - m);
        sw[warp][t] = we;
        s += we;
    }
    s = warpSum(s);
    float inv = 1.f / s;
    __syncwarp();

    bool hi = lane < (NCLS - 32);
    float accA[4] = {0.f, 0.f, 0.f, 0.f};
    float accB[2] = {0.f, 0.f};
    int t = 0;
    for (; t + 4 <= len; t += 4) {
#pragma unroll
        for (int u = 0; u < 4; u++) {
            int j = sc[warp][t + u];
            float wgt = sw[warp][t + u];
            const float* wr = g_Who + (size_t)j * NCLS;
            accA[u] += wgt * wr[lane];
            if (hi) accB[u & 1] += wgt * wr[32 + lane];
        }
    }
    for (; t < len; t++) {
        int j = sc[warp][t];
        float wgt = sw[warp][t];
        const float* wr = g_Who + (size_t)j * NCLS;
        accA[0] += wgt * wr[lane];
        if (hi) accB[0] += wgt * wr[32 + lane];
    }
    float v0 = elu((accA[0] + accA[1] + accA[2] + accA[3]) * inv);
    float v1 = hi ? elu((accB[0] + accB[1]) * inv) : -1e30f;
    float mm = warpMax(fmaxf(v0, v1));
    float se = expf(v0 - mm) + (hi ? expf(v1 - mm) : 0.f);
    se = warpSum(se);
    float lse = logf(se);
    out[(size_t)i * NCLS + lane] = v0 - mm - lse;
    if (hi) out[(size_t)i * NCLS + 32 + lane] = v1 - mm - lse;
}

// ---------------- launch ----------------
extern "C" void kernel_launch(void* const* d_in, const int* in_sizes, int n_in,
                              void* d_out, int out_size) {
    const float* x   = (const float*)d_in[0];
    const float* adj = (const float*)d_in[1];
    const float* W   = (const float*)d_in[2];
    const float* a1  = (const float*)d_in[3];
    const float* a2  = (const float*)d_in[4];
    const float* Wo  = (const float*)d_in[5];
    const float* ao1 = (const float*)d_in[6];
    const float* ao2 = (const float*)d_in[7];
    float* out = (float*)d_out;
    (void)in_sizes; (void)n_in; (void)out_size;

    cudaFuncSetAttribute(fused_gemm_csr,
                         cudaFuncAttributeMaxDynamicSharedMemorySize, FUSED_SMEM);

    conv_kernel<<<296, 256>>>(x, W);
    fused_gemm_csr<<<GEMM_BLOCKS + CSR_BLOCKS, 256, FUSED_SMEM>>>(adj, a1, a2);
    attn_heads_kernel<<<dim3(N_NODES / 8, HEADS), 256>>>();
    out_proj_kernel<<<N_NODES / 8, 256>>>(Wo, ao1, ao2);
    attn_out_kernel<<<N_NODES / 8, 256>>>(out);
}

// round 17
// speedup vs baseline: 1.5606x; 1.0102x over previous
#include <cuda_runtime.h>
#include <cuda_bf16.h>
#include <cstdint>

#define N_NODES 6144
#define HEADS 4
#define FH 64
#define FIN 512
#define NCLS 40
#define MAX_DEG 128
#define NCAT 256

#define GEMM_BLOCKS 96
#define CSR_BLOCKS 1536          // 4 rows per block
#define FUSED_SMEM 49216

// ---------------- device scratch ----------------
__device__ int   g_col[N_NODES * MAX_DEG];
__device__ int   g_len[N_NODES];
__device__ float g_Wh[HEADS * N_NODES * FH];   // [head][node][fh]
__device__ float g_f1[HEADS * N_NODES];
__device__ float g_f2[HEADS * N_NODES];
__device__ float g_hcat[N_NODES * NCAT];       // [node][head*64+fh]
__device__ float g_Who[N_NODES * NCLS];
__device__ float g_f1o[N_NODES];
__device__ float g_f2o[N_NODES];
__device__ __nv_bfloat16 g_xhi[N_NODES * FIN];
__device__ __nv_bfloat16 g_xlo[N_NODES * FIN];
__device__ __nv_bfloat16 g_Whi[NCAT * FIN];    // [n=head*64+fh][k]
__device__ __nv_bfloat16 g_Wlo[NCAT * FIN];
__device__ __nv_bfloat16 g_Wohi[64 * NCAT];    // [n(pad64)][k=256]
__device__ __nv_bfloat16 g_Wolo[64 * NCAT];

// ---------------- helpers ----------------
__device__ __forceinline__ float warpMax(float v) {
#pragma unroll
    for (int o = 16; o; o >>= 1) v = fmaxf(v, __shfl_xor_sync(0xffffffffu, v, o));
    return v;
}
__device__ __forceinline__ float warpSum(float v) {
#pragma unroll
    for (int o = 16; o; o >>= 1) v += __shfl_xor_sync(0xffffffffu, v, o);
    return v;
}
__device__ __forceinline__ float lrelu(float x) { return x > 0.f ? x : 0.2f * x; }
__device__ __forceinline__ float elu(float x) { return x > 0.f ? x : (expf(x) - 1.f); }

__device__ __forceinline__ void ldsm_x4(uint32_t* r, uint32_t addr) {
    asm volatile("ldmatrix.sync.aligned.m8n8.x4.shared.b16 {%0,%1,%2,%3}, [%4];"
        : "=r"(r[0]), "=r"(r[1]), "=r"(r[2]), "=r"(r[3]) : "r"(addr));
}
__device__ __forceinline__ void mma16816(float* d, const uint32_t* a, const uint32_t* b) {
    asm volatile("mma.sync.aligned.m16n8k16.row.col.f32.bf16.bf16.f32 "
        "{%0,%1,%2,%3}, {%4,%5,%6,%7}, {%8,%9}, {%0,%1,%2,%3};"
        : "+f"(d[0]), "+f"(d[1]), "+f"(d[2]), "+f"(d[3])
        : "r"(a[0]), "r"(a[1]), "r"(a[2]), "r"(a[3]), "r"(b[0]), "r"(b[1]));
}
__device__ __forceinline__ uint32_t pack_bf16(float a, float b) {
    return ((uint32_t)__bfloat16_as_ushort(__float2bfloat16(b)) << 16) |
           (uint32_t)__bfloat16_as_ushort(__float2bfloat16(a));
}
__device__ __forceinline__ float bf_hi(float v) {
    return __bfloat162float(__float2bfloat16(v));
}
#define CP_ASYNC16(dst, src) \
    asm volatile("cp.async.cg.shared.global [%0], [%1], 16;" :: "r"(dst), "l"(src) : "memory")
#define CP_COMMIT() asm volatile("cp.async.commit_group;" ::: "memory")
#define CP_WAIT1()  asm volatile("cp.async.wait_group 1;" ::: "memory")
#define CP_WAIT0()  asm volatile("cp.async.wait_group 0;" ::: "memory")

// ============ K0: x hi/lo split + W transpose/split + Wo transpose/split ============
__global__ __launch_bounds__(256) void conv_kernel(
    const float* __restrict__ x, const float* __restrict__ W,
    const float* __restrict__ Wo) {
    int tid = blockIdx.x * 256 + threadIdx.x;
    int stride = gridDim.x * 256;
    const float4* x4 = reinterpret_cast<const float4*>(x);
    for (int i = tid; i < N_NODES * FIN / 4; i += stride) {
        float4 v = x4[i];
        float vv[4] = {v.x, v.y, v.z, v.w};
#pragma unroll
        for (int u = 0; u < 4; u++) {
            __nv_bfloat16 h = __float2bfloat16(vv[u]);
            g_xhi[i * 4 + u] = h;
            g_xlo[i * 4 + u] = __float2bfloat16(vv[u] - __bfloat162float(h));
        }
    }
    for (int i = tid; i < NCAT * FIN; i += stride) {
        int n = i >> 9;
        int k = i & (FIN - 1);
        int head = n >> 6, fh = n & 63;
        float v = W[((size_t)head * FIN + k) * FH + fh];
        g_Whi[i] = __float2bfloat16(v);
        g_Wlo[i] = __float2bfloat16(v - bf_hi(v));
    }
    for (int i = tid; i < 64 * NCAT; i += stride) {
        int n = i >> 8;
        int k = i & (NCAT - 1);
        float v = (n < NCLS) ? Wo[k * NCLS + n] : 0.f;
        g_Wohi[i] = __float2bfloat16(v);
        g_Wolo[i] = __float2bfloat16(v - bf_hi(v));
    }
}

// ============ K1: fused HMMA GEMM (+f1/f2 epilogue) + cp.async CSR scan ============
#define SROW 80
#define NCHUNK 48   // 3 segments x 16 k-chunks of 32

__global__ __launch_bounds__(256) void fused_gemm_csr(
    const float* __restrict__ adj,
    const float* __restrict__ a1, const float* __restrict__ a2) {
    extern __shared__ __align__(16) char smem_u[];
    int tid = threadIdx.x;
    int lane = tid & 31, wid = tid >> 5;

    if (blockIdx.x < GEMM_BLOCKS) {
        char* sAp[2] = {smem_u, smem_u + 10240};
        char* sBp[2] = {smem_u + 20480, smem_u + 30720};
        float* sa1f = reinterpret_cast<float*>(smem_u + 40960);
        float* sa2f = reinterpret_cast<float*>(smem_u + 41984);
        sa1f[tid] = a1[tid];
        sa2f[tid] = a2[tid];

        int wm = wid & 3, wn = wid >> 2;
        int m0 = (blockIdx.x >> 1) * 128;
        int nh = blockIdx.x & 1;
        const __nv_bfloat16* Alist[3] = {g_xhi, g_xlo, g_xhi};
        const __nv_bfloat16* Blist[3] = {g_Whi, g_Whi, g_Wlo};

        int crow = tid >> 1;
        int khalf = tid & 1;

        float acc[2][8][4];
#pragma unroll
        for (int i = 0; i < 2; i++)
#pragma unroll
            for (int j = 0; j < 8; j++)
#pragma unroll
                for (int q = 0; q < 4; q++) acc[i][j][q] = 0.f;

        int g = lane >> 3;
        int arow_lo = (lane & 7) + (g & 1) * 8;
        int ach_sel = g >> 1;
        int brow_add = (g >> 1) * 8;
        int bch_sel = g & 1;

        uint32_t sAb[2], sBb[2];
        sAb[0] = (uint32_t)__cvta_generic_to_shared(sAp[0]);
        sAb[1] = (uint32_t)__cvta_generic_to_shared(sAp[1]);
        sBb[0] = (uint32_t)__cvta_generic_to_shared(sBp[0]);
        sBb[1] = (uint32_t)__cvta_generic_to_shared(sBp[1]);

        {
            const uint4* ap = reinterpret_cast<const uint4*>(
                Alist[0] + (size_t)(m0 + crow) * FIN) + khalf * 2;
            const uint4* bp = reinterpret_cast<const uint4*>(
                Blist[0] + (size_t)(nh * 128 + crow) * FIN) + khalf * 2;
            uint4 a0 = ap[0], a1v = ap[1], b0 = bp[0], b1 = bp[1];
            char* ab = sAp[0] + crow * SROW + khalf * 32;
            char* bb = sBp[0] + crow * SROW + khalf * 32;
            *reinterpret_cast<uint4*>(ab) = a0;
            *reinterpret_cast<uint4*>(ab + 16) = a1v;
            *reinterpret_cast<uint4*>(bb) = b0;
            *reinterpret_cast<uint4*>(bb + 16) = b1;
        }
        __syncthreads();

        uint4 prA[2], prB[2];
        for (int it = 0; it < NCHUNK; it++) {
            int buf = it & 1;
            bool more = (it + 1 < NCHUNK);
            if (more) {
                int nit = it + 1;
                int seg = nit >> 4;
                int k0 = (nit & 15) * 32;
                const uint4* ap = reinterpret_cast<const uint4*>(
                    Alist[seg] + (size_t)(m0 + crow) * FIN + k0) + khalf * 2;
                const uint4* bp = reinterpret_cast<const uint4*>(
                    Blist[seg] + (size_t)(nh * 128 + crow) * FIN + k0) + khalf * 2;
                prA[0] = ap[0]; prA[1] = ap[1];
                prB[0] = bp[0]; prB[1] = bp[1];
            }
#pragma unroll
            for (int kt = 0; kt < 2; kt++) {
                uint32_t afr[2][4];
#pragma unroll
                for (int mi = 0; mi < 2; mi++) {
                    int row = wm * 32 + mi * 16 + arow_lo;
                    int ch = kt * 2 + ach_sel;
                    ldsm_x4(afr[mi], sAb[buf] + row * SROW + ch * 16);
                }
                uint32_t bfr[4][4];
#pragma unroll
                for (int ni4 = 0; ni4 < 4; ni4++) {
                    int nrow = wn * 64 + ni4 * 16 + (lane & 7) + brow_add;
                    int ch = kt * 2 + bch_sel;
                    ldsm_x4(bfr[ni4], sBb[buf] + nrow * SROW + ch * 16);
                }
#pragma unroll
                for (int mi = 0; mi < 2; mi++)
#pragma unroll
                    for (int ni4 = 0; ni4 < 4; ni4++) {
                        mma16816(acc[mi][ni4 * 2], afr[mi], &bfr[ni4][0]);
                        mma16816(acc[mi][ni4 * 2 + 1], afr[mi], &bfr[ni4][2]);
                    }
            }
            if (more) {
                int nb = buf ^ 1;
                char* ab = sAp[nb] + crow * SROW + khalf * 32;
                char* bb = sBp[nb] + crow * SROW + khalf * 32;
                *reinterpret_cast<uint4*>(ab) = prA[0];
                *reinterpret_cast<uint4*>(ab + 16) = prA[1];
                *reinterpret_cast<uint4*>(bb) = prB[0];
                *reinterpret_cast<uint4*>(bb + 16) = prB[1];
            }
            __syncthreads();
        }

        int h = nh * 2 + wn;
#pragma unroll
        for (int mi = 0; mi < 2; mi++) {
#pragma unroll
            for (int ni = 0; ni < 8; ni++) {
                int row = m0 + wm * 32 + mi * 16 + (lane >> 2);
                int col = nh * 128 + wn * 64 + ni * 8 + (lane & 3) * 2;
                int head = col >> 6, fh = col & 63;
                float* base = g_Wh + (size_t)head * N_NODES * FH + fh;
                *reinterpret_cast<float2*>(base + (size_t)row * FH) =
                    make_float2(acc[mi][ni][0], acc[mi][ni][1]);
                *reinterpret_cast<float2*>(base + (size_t)(row + 8) * FH) =
                    make_float2(acc[mi][ni][2], acc[mi][ni][3]);
            }
            float p1a = 0.f, p2a = 0.f, p1b = 0.f, p2b = 0.f;
#pragma unroll
            for (int ni = 0; ni < 8; ni++) {
                int c0 = ni * 8 + (lane & 3) * 2;
                float A0 = sa1f[h * 64 + c0], A1 = sa1f[h * 64 + c0 + 1];
                float B0 = sa2f[h * 64 + c0], B1 = sa2f[h * 64 + c0 + 1];
                p1a += acc[mi][ni][0] * A0 + acc[mi][ni][1] * A1;
                p2a += acc[mi][ni][0] * B0 + acc[mi][ni][1] * B1;
                p1b += acc[mi][ni][2] * A0 + acc[mi][ni][3] * A1;
                p2b += acc[mi][ni][2] * B0 + acc[mi][ni][3] * B1;
            }
            p1a += __shfl_down_sync(0xffffffffu, p1a, 2, 4);
            p1a += __shfl_down_sync(0xffffffffu, p1a, 1, 4);
            p2a += __shfl_down_sync(0xffffffffu, p2a, 2, 4);
            p2a += __shfl_down_sync(0xffffffffu, p2a, 1, 4);
            p1b += __shfl_down_sync(0xffffffffu, p1b, 2, 4);
            p1b += __shfl_down_sync(0xffffffffu, p1b, 1, 4);
            p2b += __shfl_down_sync(0xffffffffu, p2b, 2, 4);
            p2b += __shfl_down_sync(0xffffffffu, p2b, 1, 4);
            if ((lane & 3) == 0) {
                int row = m0 + wm * 32 + mi * 16 + (lane >> 2);
                g_f1[h * N_NODES + row] = p1a;
                g_f2[h * N_NODES + row] = p2a;
                g_f1[h * N_NODES + row + 8] = p1b;
                g_f2[h * N_NODES + row + 8] = p2b;
            }
        }
    } else {
        char* bufs[2] = {smem_u, smem_u + 24576};
        int* warr = reinterpret_cast<int*>(smem_u + 49152);
        int brow = (blockIdx.x - GEMM_BLOCKS) * 4;

        {
            const char* src = reinterpret_cast<const char*>(adj + (size_t)brow * N_NODES);
            uint32_t d = (uint32_t)__cvta_generic_to_shared(bufs[0]);
#pragma unroll
            for (int u = 0; u < 6; u++)
                CP_ASYNC16(d + (tid + u * 256) * 16, src + (size_t)(tid + u * 256) * 16);
            CP_COMMIT();
        }
        for (int r = 0; r < 4; r++) {
            int buf = r & 1;
            if (r < 3) {
                const char* src = reinterpret_cast<const char*>(
                    adj + (size_t)(brow + r + 1) * N_NODES);
                uint32_t d = (uint32_t)__cvta_generic_to_shared(bufs[buf ^ 1]);
#pragma unroll
                for (int u = 0; u < 6; u++)
                    CP_ASYNC16(d + (tid + u * 256) * 16, src + (size_t)(tid + u * 256) * 16);
                CP_COMMIT();
                CP_WAIT1();
            } else {
                CP_WAIT0();
            }
            __syncthreads();

            const float4* bp = reinterpret_cast<const float4*>(bufs[buf]);
            float4 v[6];
#pragma unroll
            for (int u = 0; u < 6; u++) v[u] = bp[wid * 192 + u * 32 + lane];
            int msk[6];
            int cnt = 0;
#pragma unroll
            for (int u = 0; u < 6; u++) {
                int m = (v[u].x > 0.f) | ((v[u].y > 0.f) << 1) |
                        ((v[u].z > 0.f) << 2) | ((v[u].w > 0.f) << 3);
                msk[u] = m;
                cnt += __popc(m);
            }
            int incl = cnt;
#pragma unroll
            for (int o = 1; o < 32; o <<= 1) {
                int n = __shfl_up_sync(0xffffffffu, incl, o);
                if (lane >= o) incl += n;
            }
            if (lane == 31) warr[wid] = incl;
            __syncthreads();
            int bpre = 0;
#pragma unroll
            for (int w2 = 0; w2 < 8; w2++) bpre += (w2 < wid) ? warr[w2] : 0;
            int total8 = warr[0] + warr[1] + warr[2] + warr[3] +
                         warr[4] + warr[5] + warr[6] + warr[7];
            int row = brow + r;
            int* outp = g_col + (size_t)row * MAX_DEG;
            int pos = bpre + incl - cnt;
#pragma unroll
            for (int u = 0; u < 6; u++) {
                int m = msk[u];
                int col0 = (wid * 192 + u * 32 + lane) * 4;
                if (m & 1) { if (pos < MAX_DEG) outp[pos] = col0;     pos++; }
                if (m & 2) { if (pos < MAX_DEG) outp[pos] = col0 + 1; pos++; }
                if (m & 4) { if (pos < MAX_DEG) outp[pos] = col0 + 2; pos++; }
                if (m & 8) { if (pos < MAX_DEG) outp[pos] = col0 + 3; pos++; }
            }
            if (tid == 0) g_len[row] = total8 < MAX_DEG ? total8 : MAX_DEG;
            __syncthreads();
        }
    }
}

// ============ K2: per-head sparse attention + ELU -> hcat ============
__global__ __launch_bounds__(256) void attn_heads_kernel() {
    __shared__ float sw[8][MAX_DEG];
    __shared__ int   sc[8][MAX_DEG];
    int warp = threadIdx.x >> 5, lane = threadIdx.x & 31;
    int h = blockIdx.y;
    int i = blockIdx.x * 8 + warp;
    int len = g_len[i];
    const int* cols = g_col + (size_t)i * MAX_DEG;
    float f1i = g_f1[h * N_NODES + i];
    const float* f2h = g_f2 + (size_t)h * N_NODES;

    float m = -1e30f;
    for (int t = lane; t < len; t += 32) {
        int j = __ldg(cols + t);
        sc[warp][t] = j;
        float e = lrelu(f1i + f2h[j]);
        sw[warp][t] = e;
        m = fmaxf(m, e);
    }
    m = warpMax(m);
    float s = 0.f;
    for (int t = lane; t < len; t += 32) {
        float we = expf(sw[warp][t] - m);
        sw[warp][t] = we;
        s += we;
    }
    s = warpSum(s);
    float inv = 1.f / s;
    __syncwarp();

    const float* WhH = g_Wh + (size_t)h * N_NODES * FH;
    float2 a0 = {0.f, 0.f}, a1v = {0.f, 0.f}, a2v = {0.f, 0.f}, a3 = {0.f, 0.f};
    int t = 0;
    for (; t + 4 <= len; t += 4) {
        int j0 = sc[warp][t], j1 = sc[warp][t + 1];
        int j2 = sc[warp][t + 2], j3 = sc[warp][t + 3];
        float w0 = sw[warp][t], w1 = sw[warp][t + 1];
        float w2 = sw[warp][t + 2], w3 = sw[warp][t + 3];
        float2 v0 = *(reinterpret_cast<const float2*>(WhH + (size_t)j0 * FH) + lane);
        float2 v1 = *(reinterpret_cast<const float2*>(WhH + (size_t)j1 * FH) + lane);
        float2 v2 = *(reinterpret_cast<const float2*>(WhH + (size_t)j2 * FH) + lane);
        float2 v3 = *(reinterpret_cast<const float2*>(WhH + (size_t)j3 * FH) + lane);
        a0.x += w0 * v0.x; a0.y += w0 * v0.y;
        a1v.x += w1 * v1.x; a1v.y += w1 * v1.y;
        a2v.x += w2 * v2.x; a2v.y += w2 * v2.y;
        a3.x += w3 * v3.x; a3.y += w3 * v3.y;
    }
    for (; t < len; t++) {
        int j0 = sc[warp][t];
        float w0 = sw[warp][t];
        float2 v0 = *(reinterpret_cast<const float2*>(WhH + (size_t)j0 * FH) + lane);
        a0.x += w0 * v0.x; a0.y += w0 * v0.y;
    }
    float rx = a0.x + a1v.x + a2v.x + a3.x;
    float ry = a0.y + a1v.y + a2v.y + a3.y;
    float2 o = make_float2(elu(rx * inv), elu(ry * inv));
    *(reinterpret_cast<float2*>(g_hcat + (size_t)i * NCAT + h * FH) + lane) = o;
}

// ============ K3: HMMA out-proj: Who = hcat @ Wo (+f1o/f2o epilogue) ============
#define ONCHUNK 24   // 3 segments x 8 k-chunks of 32 (K=256)

__global__ __launch_bounds__(256) void out_proj_mma(
    const float* __restrict__ ao1, const float* __restrict__ ao2) {
    __shared__ __align__(16) char sA[2][128 * SROW];   // 20480
    __shared__ __align__(16) char sB[2][64 * SROW];    // 10240
    __shared__ float sao1[64], sao2[64];
    __shared__ float sp1[2][128], sp2[2][128];
    int tid = threadIdx.x;
    int lane = tid & 31, wid = tid >> 5;
    int wm = wid & 3, wn = wid >> 2;     // wm 0..3 (m), wn 0..1 (n-half)
    int m0 = blockIdx.x * 128;

    if (tid < 64) {
        sao1[tid] = (tid < NCLS) ? ao1[tid] : 0.f;
        sao2[tid] = (tid < NCLS) ? ao2[tid] : 0.f;
    }

    const __nv_bfloat16* Blist[3] = {g_Wohi, g_Wohi, g_Wolo};
    int crow = tid >> 1;
    int khalf = tid & 1;
    int brow = tid >> 2;       // 0..63
    int bq = tid & 3;          // 16B quarter of 64B chunk-row

    float acc[2][4][4];
#pragma unroll
    for (int i = 0; i < 2; i++)
#pragma unroll
        for (int j = 0; j < 4; j++)
#pragma unroll
            for (int q = 0; q < 4; q++) acc[i][j][q] = 0.f;

    int g = lane >> 3;
    int arow_lo = (lane & 7) + (g & 1) * 8;
    int ach_sel = g >> 1;
    int brow_add = (g >> 1) * 8;
    int bch_sel = g & 1;

    uint32_t sAb[2], sBb[2];
    sAb[0] = (uint32_t)__cvta_generic_to_shared(sA[0]);
    sAb[1] = (uint32_t)__cvta_generic_to_shared(sA[1]);
    sBb[0] = (uint32_t)__cvta_generic_to_shared(sB[0]);
    sBb[1] = (uint32_t)__cvta_generic_to_shared(sB[1]);

    const float4* arow = reinterpret_cast<const float4*>(
        g_hcat + (size_t)(m0 + crow) * NCAT) + khalf * 4;

    // prologue: chunk 0 (seg 0 = hi)
    {
        float4 fa[4];
#pragma unroll
        for (int q = 0; q < 4; q++) fa[q] = arow[q];
        uint4 bv = *(reinterpret_cast<const uint4*>(g_Wohi + (size_t)brow * NCAT) + bq);
        uint32_t pk[8];
#pragma unroll
        for (int q = 0; q < 4; q++) {
            pk[q * 2]     = pack_bf16(fa[q].x, fa[q].y);
            pk[q * 2 + 1] = pack_bf16(fa[q].z, fa[q].w);
        }
        char* ab = sA[0] + crow * SROW + khalf * 32;
        *reinterpret_cast<uint4*>(ab)      = make_uint4(pk[0], pk[1], pk[2], pk[3]);
        *reinterpret_cast<uint4*>(ab + 16) = make_uint4(pk[4], pk[5], pk[6], pk[7]);
        *reinterpret_cast<uint4*>(sB[0] + brow * SROW + bq * 16) = bv;
    }
    __syncthreads();

    float4 prA[4];
    uint4 prB;
    for (int it = 0; it < ONCHUNK; it++) {
        int buf = it & 1;
        bool more = (it + 1 < ONCHUNK);
        int nseg = 0;
        if (more) {
            int nit = it + 1;
            nseg = nit >> 3;
            int k0 = (nit & 7) * 32;
#pragma unroll
            for (int q = 0; q < 4; q++) prA[q] = arow[(k0 >> 2) + q];
            prB = *(reinterpret_cast<const uint4*>(
                Blist[nseg] + (size_t)brow * NCAT + k0) + bq);
        }
#pragma unroll
        for (int kt = 0; kt < 2; kt++) {
            uint32_t afr[2][4];
#pragma unroll
            for (int mi = 0; mi < 2; mi++) {
                int row = wm * 32 + mi * 16 + arow_lo;
                int ch = kt * 2 + ach_sel;
                ldsm_x4(afr[mi], sAb[buf] + row * SROW + ch * 16);
            }
            uint32_t bfr[2][4];
#pragma unroll
            for (int ni4 = 0; ni4 < 2; ni4++) {
                int nrow = wn * 32 + ni4 * 16 + (lane & 7) + brow_add;
                int ch = kt * 2 + bch_sel;
                ldsm_x4(bfr[ni4], sBb[buf] + nrow * SROW + ch * 16);
            }
#pragma unroll
            for (int mi = 0; mi < 2; mi++)
#pragma unroll
                for (int ni4 = 0; ni4 < 2; ni4++) {
                    mma16816(acc[mi][ni4 * 2], afr[mi], &bfr[ni4][0]);
                    mma16816(acc[mi][ni4 * 2 + 1], afr[mi], &bfr[ni4][2]);
                }
        }
        if (more) {
            int nb = buf ^ 1;
            uint32_t pk[8];
            if (nseg == 1) {
#pragma unroll
                for (int q = 0; q < 4; q++) {
                    pk[q * 2]     = pack_bf16(prA[q].x - bf_hi(prA[q].x),
                                              prA[q].y - bf_hi(prA[q].y));
                    pk[q * 2 + 1] = pack_bf16(prA[q].z - bf_hi(prA[q].z),
                                              prA[q].w - bf_hi(prA[q].w));
                }
            } else {
#pragma unroll
                for (int q = 0; q < 4; q++) {
                    pk[q * 2]     = pack_bf16(prA[q].x, prA[q].y);
                    pk[q * 2 + 1] = pack_bf16(prA[q].z, prA[q].w);
                }
            }
            char* ab = sA[nb] + crow * SROW + khalf * 32;
            *reinterpret_cast<uint4*>(ab)      = make_uint4(pk[0], pk[1], pk[2], pk[3]);
            *reinterpret_cast<uint4*>(ab + 16) = make_uint4(pk[4], pk[5], pk[6], pk[7]);
            *reinterpret_cast<uint4*>(sB[nb] + brow * SROW + bq * 16) = prB;
        }
        __syncthreads();
    }

    // epilogue: store Who (cols<40) + f1o/f2o via quad + cross-warp reduce
#pragma unroll
    for (int mi = 0; mi < 2; mi++) {
        int row_l = wm * 32 + mi * 16 + (lane >> 2);
        float p1a = 0.f, p2a = 0.f, p1b = 0.f, p2b = 0.f;
#pragma unroll
        for (int ni = 0; ni < 4; ni++) {
            int col = wn * 32 + ni * 8 + (lane & 3) * 2;
            if (col < NCLS) {
                *reinterpret_cast<float2*>(g_Who + (size_t)(m0 + row_l) * NCLS + col) =
                    make_float2(acc[mi][ni][0], acc[mi][ni][1]);
                *reinterpret_cast<float2*>(g_Who + (size_t)(m0 + row_l + 8) * NCLS + col) =
                    make_float2(acc[mi][ni][2], acc[mi][ni][3]);
            }
            float A0 = sao1[col], A1 = sao1[col + 1];
            float B0 = sao2[col], B1 = sao2[col + 1];
            p1a += acc[mi][ni][0] * A0 + acc[mi][ni][1] * A1;
            p2a += acc[mi][ni][0] * B0 + acc[mi][ni][1] * B1;
            p1b += acc[mi][ni][2] * A0 + acc[mi][ni][3] * A1;
            p2b += acc[mi][ni][2] * B0 + acc[mi][ni][3] * B1;
        }
        p1a += __shfl_down_sync(0xffffffffu, p1a, 2, 4);
        p1a += __shfl_down_sync(0xffffffffu, p1a, 1, 4);
        p2a += __shfl_down_sync(0xffffffffu, p2a, 2, 4);
        p2a += __shfl_down_sync(0xffffffffu, p2a, 1, 4);
        p1b += __shfl_down_sync(0xffffffffu, p1b, 2, 4);
        p1b += __shfl_down_sync(0xffffffffu, p1b, 1, 4);
        p2b += __shfl_down_sync(0xffffffffu, p2b, 2, 4);
        p2b += __shfl_down_sync(0xffffffffu, p2b, 1, 4);
        if ((lane & 3) == 0) {
            sp1[wn][row_l] = p1a;
            sp2[wn][row_l] = p2a;
            sp1[wn][row_l + 8] = p1b;
            sp2[wn][row_l + 8] = p2b;
        }
    }
    __syncthreads();
    if (tid < 128) {
        g_f1o[m0 + tid] = sp1[0][tid] + sp1[1][tid];
        g_f2o[m0 + tid] = sp2[0][tid] + sp2[1][tid];
    }
}

// ============ K4: output sparse attention + ELU + log_softmax ============
__global__ __launch_bounds__(256) void attn_out_kernel(float* __restrict__ out) {
    __shared__ float sw[8][MAX_DEG];
    __shared__ int   sc[8][MAX_DEG];
    int warp = threadIdx.x >> 5, lane = threadIdx.x & 31;
    int i = blockIdx.x * 8 + warp;
    int len = g_len[i];
    const int* cols = g_col + (size_t)i * MAX_DEG;
    float f1i = g_f1o[i];

    float m = -1e30f;
    for (int t = lane; t < len; t += 32) {
        int j = __ldg(cols + t);
        sc[warp][t] = j;
        float e = lrelu(f1i + g_f2o[j]);
        sw[warp][t] = e;
        m = fmaxf(m, e);
    }
    m = warpMax(m);
    float s = 0.f;
    for (int t = lane; t < len; t += 32) {
        float we = expf(sw[warp][t] - m);
        sw[warp][t] = we;
        s += we;
    }
    s = warpSum(s);
    float inv = 1.f / s;
    __syncwarp();

    bool hi = lane < (NCLS - 32);
    float accA[4] = {0.f, 0.f, 0.f, 0.f};
    float accB[2] = {0.f, 0.f};
    int t = 0;
    for (; t + 4 <= len; t += 4) {
#pragma unroll
        for (int u = 0; u < 4; u++) {
            int j = sc[warp][t + u];
            float wgt = sw[warp][t + u];
            const float* wr = g_Who + (size_t)j * NCLS;
            accA[u] += wgt * wr[lane];
            if (hi) accB[u & 1] += wgt * wr[32 + lane];
        }
    }
    for (; t < len; t++) {
        int j = sc[warp][t];
        float wgt = sw[warp][t];
        const float* wr = g_Who + (size_t)j * NCLS;
        accA[0] += wgt * wr[lane];
        if (hi) accB[0] += wgt * wr[32 + lane];
    }
    float v0 = elu((accA[0] + accA[1] + accA[2] + accA[3]) * inv);
    float v1 = hi ? elu((accB[0] + accB[1]) * inv) : -1e30f;
    float mm = warpMax(fmaxf(v0, v1));
    float se = expf(v0 - mm) + (hi ? expf(v1 - mm) : 0.f);
    se = warpSum(se);
    float lse = logf(se);
    out[(size_t)i * NCLS + lane] = v0 - mm - lse;
    if (hi) out[(size_t)i * NCLS + 32 + lane] = v1 - mm - lse;
}

// ---------------- launch ----------------
extern "C" void kernel_launch(void* const* d_in, const int* in_sizes, int n_in,
                              void* d_out, int out_size) {
    const float* x   = (const float*)d_in[0];
    const float* adj = (const float*)d_in[1];
    const float* W   = (const float*)d_in[2];
    const float* a1  = (const float*)d_in[3];
    const float* a2  = (const float*)d_in[4];
    const float* Wo  = (const float*)d_in[5];
    const float* ao1 = (const float*)d_in[6];
    const float* ao2 = (const float*)d_in[7];
    float* out = (float*)d_out;
    (void)in_sizes; (void)n_in; (void)out_size;

    cudaFuncSetAttribute(fused_gemm_csr,
                         cudaFuncAttributeMaxDynamicSharedMemorySize, FUSED_SMEM);

    conv_kernel<<<296, 256>>>(x, W, Wo);
    fused_gemm_csr<<<GEMM_BLOCKS + CSR_BLOCKS, 256, FUSED_SMEM>>>(adj, a1, a2);
    attn_heads_kernel<<<dim3(N_NODES / 8, HEADS), 256>>>();
    out_proj_mma<<<N_NODES / 128, 256>>>(ao1, ao2);
    attn_out_kernel<<<N_NODES / 8, 256>>>(out);
}